// round 1
// baseline (speedup 1.0000x reference)
#include <cuda_runtime.h>
#include <math.h>

#define N_NODES_C 20000
#define N_EDGES_C 100000
#define WNUM_C 2304
// smem: 16*2304 fc2 floats + 160 fc1 floats
#define SMEM_FLOATS (16 * 2304 + 160)
#define SMEM_BYTES (SMEM_FLOATS * 4)

// C0 = C1 = C2 = 1/sqrt(48), C3 = 0.25 (derived from MUL_S=32, MUL_V=16)
#define C0F 0.14433756729740643f
#define C1F 0.14433756729740643f
#define C2F 0.14433756729740643f
#define C3F 0.25f

__global__ __launch_bounds__(256, 1)
void tp_fused_kernel(const float* __restrict__ feature,
                     const int*   __restrict__ edge,
                     const float* __restrict__ ele,
                     const float* __restrict__ esh,
                     const float* __restrict__ fw1,
                     const float* __restrict__ fw2,
                     float*       __restrict__ out,
                     float silu_c)
{
    extern __shared__ float smem[];
    float* sW  = smem;             // [16][2304] normalized fc_w2 (x0.25)
    float* sW1 = smem + 16 * 2304; // [10][16]  normalized fc_w1 (x 1/sqrt(10))

    // ---- stage weights into shared ----
    {
        const float4* src = (const float4*)fw2;
        float4* dst = (float4*)sW;
        for (int i = threadIdx.x; i < (16 * 2304) / 4; i += blockDim.x) {
            float4 v = src[i];
            v.x *= 0.25f; v.y *= 0.25f; v.z *= 0.25f; v.w *= 0.25f;
            dst[i] = v;
        }
        const float inb = 0.31622776601683794f; // 1/sqrt(10)
        for (int i = threadIdx.x; i < 160; i += blockDim.x)
            sW1[i] = fw1[i] * inb;
    }
    __syncthreads();

    const int lane   = threadIdx.x & 31;
    const int warp   = threadIdx.x >> 5;
    const int gwarp  = blockIdx.x * (blockDim.x >> 5) + warp;
    const int nwarps = gridDim.x * (blockDim.x >> 5);
    const int nchunks = N_EDGES_C / 32; // 3125 exactly

    for (int c = gwarp; c < nchunks; c += nwarps) {
        const int e = c * 32 + lane;

        // ---- h = silu_c * silu(ele @ fc_w1n) ----
        float h[16];
        {
            float x[10];
            const float* er = ele + e * 10;
            #pragma unroll
            for (int j = 0; j < 10; j++) x[j] = er[j];
            #pragma unroll
            for (int k = 0; k < 16; k++) {
                float a = 0.f;
                #pragma unroll
                for (int j = 0; j < 10; j++) a = fmaf(x[j], sW1[j * 16 + k], a);
                float sg = 1.0f / (1.0f + __expf(-a));
                h[k] = silu_c * a * sg;
            }
        }

        const int dst = edge[N_EDGES_C + e]; // edge[1][e]
        const float4* frow = (const float4*)(feature + (size_t)dst * 80);
        const float4  shv  = ((const float4*)esh)[e];
        const float s2 = shv.x, v2x = shv.y, v2y = shv.z, v2z = shv.w;

        float4* orow = (float4*)(out + (size_t)e * 80);

        // =========== Pass A: r0 (W0,s1) and t1 (W1,s1) ===========
        {
            float s1[32];
            #pragma unroll
            for (int q = 0; q < 8; q++) {
                float4 f4 = frow[q];
                s1[q*4+0] = f4.x; s1[q*4+1] = f4.y; s1[q*4+2] = f4.z; s1[q*4+3] = f4.w;
            }
            float r0[32], t1v[16];
            #pragma unroll
            for (int w = 0; w < 32; w++) r0[w] = 0.f;
            #pragma unroll
            for (int w = 0; w < 16; w++) t1v[w] = 0.f;

            #pragma unroll 1
            for (int k = 0; k < 16; k++) {
                const float* W0k = sW + k * WNUM_C;
                const float* W1k = W0k + 1024;
                const float hk = h[k];
                #pragma unroll 4
                for (int u = 0; u < 32; u++) {
                    const float f = hk * s1[u];
                    const float4* c0 = (const float4*)(W0k + u * 32);
                    #pragma unroll
                    for (int q = 0; q < 8; q++) {
                        float4 cv = c0[q];
                        r0[q*4+0] = fmaf(f, cv.x, r0[q*4+0]);
                        r0[q*4+1] = fmaf(f, cv.y, r0[q*4+1]);
                        r0[q*4+2] = fmaf(f, cv.z, r0[q*4+2]);
                        r0[q*4+3] = fmaf(f, cv.w, r0[q*4+3]);
                    }
                    const float4* c1 = (const float4*)(W1k + u * 16);
                    #pragma unroll
                    for (int q = 0; q < 4; q++) {
                        float4 cv = c1[q];
                        t1v[q*4+0] = fmaf(f, cv.x, t1v[q*4+0]);
                        t1v[q*4+1] = fmaf(f, cv.y, t1v[q*4+1]);
                        t1v[q*4+2] = fmaf(f, cv.z, t1v[q*4+2]);
                        t1v[q*4+3] = fmaf(f, cv.w, t1v[q*4+3]);
                    }
                }
            }

            // partial out_s = C0*s2*r0  (r3 term added in pass C)
            const float cs = C0F * s2;
            #pragma unroll
            for (int q = 0; q < 8; q++) {
                float4 o;
                o.x = cs * r0[q*4+0]; o.y = cs * r0[q*4+1];
                o.z = cs * r0[q*4+2]; o.w = cs * r0[q*4+3];
                orow[q] = o;
            }

            // =========== Pass B: t2 (W2,v1) and out_v ===========
            float v1[48];
            #pragma unroll
            for (int q = 0; q < 12; q++) {
                float4 f4 = frow[8 + q];
                v1[q*4+0] = f4.x; v1[q*4+1] = f4.y; v1[q*4+2] = f4.z; v1[q*4+3] = f4.w;
            }
            float t2[48];
            #pragma unroll
            for (int j = 0; j < 48; j++) t2[j] = 0.f;

            #pragma unroll 1
            for (int k = 0; k < 16; k++) {
                const float* W2k = sW + k * WNUM_C + 1536;
                const float hk = h[k];
                #pragma unroll 2
                for (int u = 0; u < 16; u++) {
                    const float fx = hk * v1[u*3+0];
                    const float fy = hk * v1[u*3+1];
                    const float fz = hk * v1[u*3+2];
                    const float4* c2 = (const float4*)(W2k + u * 16);
                    #pragma unroll
                    for (int q = 0; q < 4; q++) {
                        float4 cv = c2[q];
                        #pragma unroll
                        for (int r = 0; r < 4; r++) {
                            float cc = (r == 0) ? cv.x : (r == 1) ? cv.y : (r == 2) ? cv.z : cv.w;
                            int w = q * 4 + r;
                            t2[w*3+0] = fmaf(fx, cc, t2[w*3+0]);
                            t2[w*3+1] = fmaf(fy, cc, t2[w*3+1]);
                            t2[w*3+2] = fmaf(fz, cc, t2[w*3+2]);
                        }
                    }
                }
            }

            // out_v[w,i] = C1*t1[w]*v2[i] + C2*s2*t2[w,i]
            {
                const float c2s = C2F * s2;
                float ov[48];
                #pragma unroll
                for (int w = 0; w < 16; w++) {
                    const float a = C1F * t1v[w];
                    ov[w*3+0] = fmaf(a, v2x, c2s * t2[w*3+0]);
                    ov[w*3+1] = fmaf(a, v2y, c2s * t2[w*3+1]);
                    ov[w*3+2] = fmaf(a, v2z, c2s * t2[w*3+2]);
                }
                float4* ovp = (float4*)(out + (size_t)e * 80 + 32);
                #pragma unroll
                for (int q = 0; q < 12; q++) {
                    float4 o;
                    o.x = ov[q*4+0]; o.y = ov[q*4+1]; o.z = ov[q*4+2]; o.w = ov[q*4+3];
                    ovp[q] = o;
                }
            }

            // =========== Pass C: r3 (W3, v1.v2) ===========
            float b[16];
            #pragma unroll
            for (int u = 0; u < 16; u++)
                b[u] = fmaf(v1[u*3+0], v2x, fmaf(v1[u*3+1], v2y, v1[u*3+2] * v2z));

            float r3[32];
            #pragma unroll
            for (int w = 0; w < 32; w++) r3[w] = 0.f;

            #pragma unroll 1
            for (int k = 0; k < 16; k++) {
                const float* W3k = sW + k * WNUM_C + 1792;
                const float hk = h[k];
                #pragma unroll 2
                for (int u = 0; u < 16; u++) {
                    const float f = hk * b[u];
                    const float4* c3 = (const float4*)(W3k + u * 32);
                    #pragma unroll
                    for (int q = 0; q < 8; q++) {
                        float4 cv = c3[q];
                        r3[q*4+0] = fmaf(f, cv.x, r3[q*4+0]);
                        r3[q*4+1] = fmaf(f, cv.y, r3[q*4+1]);
                        r3[q*4+2] = fmaf(f, cv.z, r3[q*4+2]);
                        r3[q*4+3] = fmaf(f, cv.w, r3[q*4+3]);
                    }
                }
            }

            // out_s += C3 * r3 (RMW of our own earlier write — same thread)
            #pragma unroll
            for (int q = 0; q < 8; q++) {
                float4 o = orow[q];
                o.x = fmaf(C3F, r3[q*4+0], o.x);
                o.y = fmaf(C3F, r3[q*4+1], o.y);
                o.z = fmaf(C3F, r3[q*4+2], o.z);
                o.w = fmaf(C3F, r3[q*4+3], o.w);
                orow[q] = o;
            }
        }
    }
}

// Replicates the reference's numerically-integrated silu normalization
// constant exactly (double-precision trapz on the same grid). Runs on host
// at capture time — not part of the timed graph.
static float compute_silu_c()
{
    const int N = 200001;
    const double dx = 24.0 / 200000.0;
    const double inv_sqrt_2pi = 0.3989422804014326779;
    double acc = 0.0, prev = 0.0;
    for (int i = 0; i < N; i++) {
        double x = -12.0 + dx * (double)i;
        double pdf = exp(-0.5 * x * x) * inv_sqrt_2pi;
        double s = x / (1.0 + exp(-x));
        double y = s * s * pdf;
        if (i > 0) acc += 0.5 * (y + prev) * dx;
        prev = y;
    }
    return (float)(1.0 / sqrt(acc));
}

extern "C" void kernel_launch(void* const* d_in, const int* in_sizes, int n_in,
                              void* d_out, int out_size)
{
    const float* feature = (const float*)d_in[0];
    const int*   edge    = (const int*)  d_in[1];
    const float* ele     = (const float*)d_in[2];
    const float* esh     = (const float*)d_in[3];
    const float* fw1     = (const float*)d_in[4];
    const float* fw2     = (const float*)d_in[5];
    float* out = (float*)d_out;

    static float silu_c = 0.0f;
    // deterministic pure-host computation; same value every call
    silu_c = compute_silu_c();

    cudaFuncSetAttribute(tp_fused_kernel,
                         cudaFuncAttributeMaxDynamicSharedMemorySize, SMEM_BYTES);

    tp_fused_kernel<<<152, 256, SMEM_BYTES>>>(feature, edge, ele, esh, fw1, fw2,
                                              out, silu_c);
}